// round 4
// baseline (speedup 1.0000x reference)
#include <cuda_runtime.h>
#include <cstdint>

// embedding_bag(mode='mean'): B bags over a [V,64] fp32 table.
// One HALF-WARP per bag; sublane s (0..15) owns one float4 (cols 4s..4s+3).
// 16 lanes x 16B = one full 256B row per half-warp; one warp LDG.E.128
// fetches TWO rows (512B). Unroll x4 with software-pipelined index
// prefetch: next batch's indices load while current batch gathers.
__global__ __launch_bounds__(256)
void embag_mean_kernel(const void* __restrict__ indices_raw,
                       const void* __restrict__ offsets_raw,
                       const char* __restrict__ weight_bytes,
                       float* __restrict__ out,
                       int num_bags, long long total_indices) {
    const int warp_global = (int)((blockIdx.x * (unsigned)blockDim.x + threadIdx.x) >> 5);
    const int lane = threadIdx.x & 31;
    const int half = lane >> 4;
    const int sub  = lane & 15;
    const int bag  = 2 * warp_global + half;
    if (bag >= num_bags) return;

    // Base pointer pre-offset by this lane's float4 column group; row offsets
    // are then 32-bit byte offsets (V*256B = 256MB fits in u32).
    const char* __restrict__ wbase = weight_bytes + (unsigned)(sub * 16);

    // Inline dtype detection (int64 vs int32 indices): ids < 2^31, so an
    // int64 LE buffer has all odd 32-bit words zero; int32 has random ids
    // there (P[all 4 zero] ~ 1e-24). Uniform across threads; broadcast loads.
    const int* wprobe = (const int*)indices_raw;
    int allz = 1;
    #pragma unroll
    for (int k = 1; k < 9; k += 2) allz &= (__ldg(&wprobe[k]) == 0);
    const bool is64 = (allz != 0);

    const long long* __restrict__ idx64 = (const long long*)indices_raw;
    const int*       __restrict__ idx32 = (const int*)indices_raw;
    const long long* __restrict__ off64 = (const long long*)offsets_raw;
    const int*       __restrict__ off32 = (const int*)offsets_raw;

    long long start, end;
    if (is64) {
        start = __ldg(&off64[bag]);
        end   = (bag + 1 < num_bags) ? __ldg(&off64[bag + 1]) : total_indices;
    } else {
        start = (long long)__ldg(&off32[bag]);
        end   = (bag + 1 < num_bags) ? (long long)__ldg(&off32[bag + 1]) : total_indices;
    }

    float4 acc = make_float4(0.f, 0.f, 0.f, 0.f);

    long long i = start;
    if (i + 4 <= end) {
        // Prologue: load first batch of row byte-offsets.
        unsigned rc0, rc1, rc2, rc3;
        if (is64) {
            rc0 = (unsigned)__ldg(&idx64[i    ]) << 8;
            rc1 = (unsigned)__ldg(&idx64[i + 1]) << 8;
            rc2 = (unsigned)__ldg(&idx64[i + 2]) << 8;
            rc3 = (unsigned)__ldg(&idx64[i + 3]) << 8;
        } else {
            rc0 = (unsigned)__ldg(&idx32[i    ]) << 8;
            rc1 = (unsigned)__ldg(&idx32[i + 1]) << 8;
            rc2 = (unsigned)__ldg(&idx32[i + 2]) << 8;
            rc3 = (unsigned)__ldg(&idx32[i + 3]) << 8;
        }
        for (;;) {
            const bool more = (i + 8 <= end);
            unsigned rn0 = 0, rn1 = 0, rn2 = 0, rn3 = 0;
            if (more) {
                // Prefetch next batch's indices (independent of gathers below).
                if (is64) {
                    rn0 = (unsigned)__ldg(&idx64[i + 4]) << 8;
                    rn1 = (unsigned)__ldg(&idx64[i + 5]) << 8;
                    rn2 = (unsigned)__ldg(&idx64[i + 6]) << 8;
                    rn3 = (unsigned)__ldg(&idx64[i + 7]) << 8;
                } else {
                    rn0 = (unsigned)__ldg(&idx32[i + 4]) << 8;
                    rn1 = (unsigned)__ldg(&idx32[i + 5]) << 8;
                    rn2 = (unsigned)__ldg(&idx32[i + 6]) << 8;
                    rn3 = (unsigned)__ldg(&idx32[i + 7]) << 8;
                }
            }
            // 4 independent 512B row-pair gathers.
            float4 v0 = __ldg((const float4*)(wbase + rc0));
            float4 v1 = __ldg((const float4*)(wbase + rc1));
            float4 v2 = __ldg((const float4*)(wbase + rc2));
            float4 v3 = __ldg((const float4*)(wbase + rc3));
            acc.x += (v0.x + v1.x) + (v2.x + v3.x);
            acc.y += (v0.y + v1.y) + (v2.y + v3.y);
            acc.z += (v0.z + v1.z) + (v2.z + v3.z);
            acc.w += (v0.w + v1.w) + (v2.w + v3.w);
            i += 4;
            if (!more) break;
            rc0 = rn0; rc1 = rn1; rc2 = rn2; rc3 = rn3;
        }
    }
    // Scalar tail (<4 remaining).
    for (; i < end; ++i) {
        unsigned r = (is64 ? (unsigned)__ldg(&idx64[i]) : (unsigned)__ldg(&idx32[i])) << 8;
        float4 v = __ldg((const float4*)(wbase + r));
        acc.x += v.x; acc.y += v.y; acc.z += v.z; acc.w += v.w;
    }

    const long long cnt = end - start;
    const float inv = 1.0f / (float)(cnt > 0 ? cnt : 1);
    acc.x *= inv; acc.y *= inv; acc.z *= inv; acc.w *= inv;

    ((float4*)out)[(size_t)bag * 16 + sub] = acc;
}

extern "C" void kernel_launch(void* const* d_in, const int* in_sizes, int n_in,
                              void* d_out, int out_size) {
    // metadata order: indices [T], offsets [B], weight [V*D]
    const void* indices = d_in[0];
    const void* offsets = d_in[1];
    const char* weight  = (const char*)d_in[2];
    float*      out     = (float*)d_out;

    const int       num_bags      = in_sizes[1];
    const long long total_indices = in_sizes[0];

    // 2 bags per warp, 8 warps per block -> 16 bags per block.
    const int bags_per_block = 16;
    const int blocks = (num_bags + bags_per_block - 1) / bags_per_block;
    embag_mean_kernel<<<blocks, 256>>>(indices, offsets, weight, out,
                                       num_bags, total_indices);
}